// round 9
// baseline (speedup 1.0000x reference)
#include <cuda_runtime.h>
#include <cuda_bf16.h>
#include <mma.h>
#include <math.h>
#include <stdint.h>

using namespace nvcuda;

// Problem dims
#define NFREQ 211
#define NTIME 390
#define KF    422
#define KT    1170
#define NFILT 119
#define PP    224            // padded p stride per filter
#define MPAD  26880          // = 210*128 = 120*224
#define NMT   105            // fold m-tiles of 256
#define KFOLD 1170
#define K2P   1184           // stage-2 padded K (37*32)
#define NQPAD 448
#define KP    448            // stage-1 K' (S/iT interleaved)
#define NCHUNK 14            // stage-1 K' chunks of 32
#define LTILE 19             // l tiles of 64
#define S2MT  210            // stage-2 m-tiles of 128

// ---------------- device scratch ----------------
__device__ float2 g_twP[KT];
__device__ float  g_t4c[KF], g_t4s[KF];
__device__ __align__(16) float g_B1[(size_t)PP*KP];        // stage-1 coeffs [p][k']
__device__ __align__(16) float g_E2f[(size_t)K2P*NQPAD];   // rows >=1170 stay 0
__device__ float2 g_P[(size_t)NFREQ*KT];
__device__ float2 g_X[(size_t)KF*KT];
__device__ __align__(16) float g_Vre[(size_t)KT*MPAD];
__device__ __align__(16) float g_Vim[(size_t)KT*MPAD];
__device__ __align__(16) float g_Vf [(size_t)K2P*MPAD];    // rows >=1170 stay 0
__device__ float  g_Part[S2MT*4*128];

// ---------------- helpers ----------------
__device__ __forceinline__ void ffma2(float2 &c, float2 a, float2 b) {
    unsigned long long uc = *reinterpret_cast<unsigned long long*>(&c);
    unsigned long long ua = *reinterpret_cast<unsigned long long*>(&a);
    unsigned long long ub = *reinterpret_cast<unsigned long long*>(&b);
    asm("fma.rn.f32x2 %0, %1, %2, %0;" : "+l"(uc) : "l"(ua), "l"(ub));
    c = *reinterpret_cast<float2*>(&uc);
}

// ---------------- builders ----------------
__global__ void k_tw() {
    int i = blockIdx.x*256 + threadIdx.x;
    if (i < KT) { double s,c; sincospi(2.0*i/KT, &s, &c); g_twP[i] = make_float2((float)c, (float)(-s)); }
    if (i < KF) { double s,c; sincospi(2.0*i/KF, &s, &c); g_t4c[i]=(float)c; g_t4s[i]=(float)s; }
}
__global__ void k_B1() {
    int i = blockIdx.x*256 + threadIdx.x;
    if (i >= PP*KP) return;
    int p = i / KP, k = i % KP;
    int kap = k >> 1; int iss = k & 1;
    double v = 0.0;
    const double inv = 1.0/(double)KF;
    if (p < NFREQ && kap <= 211) {
        if (kap == 0)        v = iss ? 0.0 : inv;
        else if (kap == 211) v = iss ? 0.0 : ((p & 1) ? -inv : inv);
        else {
            int r = (kap*p) % KF;
            double s,c; sincospi(2.0*r/KF, &s, &c);
            v = (iss ? s : c) * inv;
        }
    }
    g_B1[i] = (float)v;
}
__global__ void k_E2() {
    int i = blockIdx.x*256 + threadIdx.x;
    if (i >= KFOLD*NQPAD) return;
    int kap = i / NQPAD, q = i % NQPAD;
    float val = 0.f;
    const float inv = 1.0f/(float)KT;
    if (q < NTIME) {
        if (kap == 0)      val = inv;
        else if (kap == 1) val = (q & 1) ? -inv : inv;
        else if (kap < 586) {
            int l = kap - 1;
            int r = (l*q) % KT;
            double s,c; sincospi(2.0*r/KT, &s, &c);
            val = (float)c * inv;
        } else {
            int l = kap - 585;
            int r = (l*q) % KT;
            double s,c; sincospi(2.0*r/KT, &s, &c);
            val = (float)(-s) * inv;
        }
    }
    g_E2f[(size_t)kap*NQPAD + q] = val;
}

// ---------------- stage 0: X = fft2(pad(100*x)) -----------------
__global__ void k_P(const float* __restrict__ x) {
    __shared__ float2 tw[KT];
    __shared__ float  xs[NTIME];
    int tid = threadIdx.x;
    for (int i = tid; i < KT; i += 256) tw[i] = g_twP[i];
    int u = blockIdx.y;
    for (int i = tid; i < NTIME; i += 256) xs[i] = x[u*NTIME + i] * 100.0f;
    __syncthreads();
    int l = blockIdx.x*256 + tid;
    if (l >= KT) return;
    float2 acc = make_float2(0.f, 0.f);
    int j = 0;
    for (int v = 0; v < NTIME; v++) {
        float xv = xs[v];
        float2 x2 = make_float2(xv, xv);
        ffma2(acc, x2, tw[j]);
        j += l; if (j >= KT) j -= KT;
    }
    g_P[(size_t)u*KT + l] = acc;
}
__global__ void k_X() {
    __shared__ float sc[KF], ss[KF];
    int tid = threadIdx.x;
    for (int i = tid; i < KF; i += 256) { sc[i]=g_t4c[i]; ss[i]=g_t4s[i]; }
    __syncthreads();
    int l = blockIdx.x*256 + tid;
    int k = blockIdx.y;
    if (l >= KT) return;
    float2 acc = make_float2(0.f, 0.f);
    int j = 0;
    for (int u = 0; u < NFREQ; u++) {
        float2 P = g_P[(size_t)u*KT + l];
        float c = sc[j], s = ss[j];
        float2 c2 = make_float2(c, c), s2 = make_float2(s, s);
        float2 Pw = make_float2(P.y, -P.x);
        ffma2(acc, c2, P);
        ffma2(acc, s2, Pw);
        j += k; if (j >= KF) j -= KF;
    }
    g_X[(size_t)k*KT + l] = acc;
}

// ---------------- stage 1: wmma tf32 single-pass GEMM ----------------
// grid (LTILE, NFILT), 256 threads (8 warps, 4M x 2N).
// Tile: M=128 (rows 0-63: Re, 64-127: Im), N=224 (p), K'=448 in 14 chunks of 32.
#define ASTR 40
#define BSTR 40
#define CSTR 232
#define SM_A 0
#define SM_B 20480
#define SM_TOT 118784          // Cs (128*232*4) overlays A/B

__global__ void __launch_bounds__(256)
k_s1mma(const float* __restrict__ Hre, const float* __restrict__ Him) {
    extern __shared__ char smem[];
    float* Ah = (float*)(smem + SM_A);
    float* Bh = (float*)(smem + SM_B);
    float* Cs = (float*)(smem);          // epilogue overlay

    int tid = threadIdx.x;
    int f  = blockIdx.y;
    int l0 = blockIdx.x * 64;

    int wid = tid >> 5;
    int wm = wid & 3, wn = wid >> 2;
    int mb = wm * 32, nb = wn * 112;

    wmma::fragment<wmma::accumulator, 16, 16, 8, float> acc[2][7];
    #pragma unroll
    for (int mi = 0; mi < 2; mi++)
        #pragma unroll
        for (int ni = 0; ni < 7; ni++) wmma::fill_fragment(acc[mi][ni], 0.0f);

    int lc = tid & 63;
    int kq = tid >> 6;
    int lg = l0 + lc;
    bool lok = (lg < KT);
    const size_t hb = (size_t)f * KF * KT;

    for (int ch = 0; ch < NCHUNK; ch++) {
        // ---- build A (fold of H*X): 16 kap x 64 l ----
        #pragma unroll
        for (int j = 0; j < 4; j++) {
            int ka = kq + j*4;
            int kg = ch*16 + ka;
            float Sx=0.f, Sy=0.f, iTx=0.f, iTy=0.f;
            if (lok && kg <= 211) {
                float2 X = g_X[(size_t)kg*KT + lg];
                float hr = Hre[hb + (size_t)kg*KT + lg];
                float hi = Him[hb + (size_t)kg*KT + lg];
                float war = hr*X.x - hi*X.y;
                float wai = hr*X.y + hi*X.x;
                if (kg >= 1 && kg <= 210) {
                    int km = KF - kg;
                    float2 X2 = g_X[(size_t)km*KT + lg];
                    float hr2 = Hre[hb + (size_t)km*KT + lg];
                    float hi2 = Him[hb + (size_t)km*KT + lg];
                    float wbr = hr2*X2.x - hi2*X2.y;
                    float wbi = hr2*X2.y + hi2*X2.x;
                    Sx = war + wbr; Sy = wai + wbi;
                    float Tx = war - wbr, Ty = wai - wbi;
                    iTx = -Ty; iTy = Tx;
                } else { Sx = war; Sy = wai; }
            }
            *(float2*)&Ah[lc*ASTR + 2*ka]      = make_float2(Sx, iTx);
            *(float2*)&Ah[(64+lc)*ASTR + 2*ka] = make_float2(Sy, iTy);
        }
        // ---- load B: 224 rows x 32 k' ----
        for (int i = tid; i < 1792; i += 256) {
            int row = i >> 3, seg = i & 7;
            float4 v = *(const float4*)&g_B1[(size_t)row*KP + ch*32 + seg*4];
            *(float4*)&Bh[row*BSTR + seg*4] = v;
        }
        __syncthreads();

        #pragma unroll
        for (int ks = 0; ks < 4; ks++) {
            wmma::fragment<wmma::matrix_a, 16, 16, 8, wmma::precision::tf32, wmma::row_major> a[2];
            wmma::fragment<wmma::matrix_b, 16, 16, 8, wmma::precision::tf32, wmma::col_major> b[7];
            #pragma unroll
            for (int mi = 0; mi < 2; mi++) {
                wmma::load_matrix_sync(a[mi], &Ah[(mb + mi*16)*ASTR + ks*8], ASTR);
                #pragma unroll
                for (int t = 0; t < a[mi].num_elements; t++)
                    a[mi].x[t] = wmma::__float_to_tf32(a[mi].x[t]);
            }
            #pragma unroll
            for (int ni = 0; ni < 7; ni++) {
                wmma::load_matrix_sync(b[ni], &Bh[(nb + ni*16)*BSTR + ks*8], BSTR);
                #pragma unroll
                for (int t = 0; t < b[ni].num_elements; t++)
                    b[ni].x[t] = wmma::__float_to_tf32(b[ni].x[t]);
            }
            #pragma unroll
            for (int mi = 0; mi < 2; mi++)
                #pragma unroll
                for (int ni = 0; ni < 7; ni++)
                    wmma::mma_sync(acc[mi][ni], a[mi], b[ni], acc[mi][ni]);
        }
        __syncthreads();
    }

    // ---- epilogue: stage f32 to smem, coalesced f32 writes ----
    #pragma unroll
    for (int mi = 0; mi < 2; mi++)
        #pragma unroll
        for (int ni = 0; ni < 7; ni++)
            wmma::store_matrix_sync(&Cs[(mb + mi*16)*CSTR + nb + ni*16], acc[mi][ni],
                                    CSTR, wmma::mem_row_major);
    __syncthreads();

    size_t fb = (size_t)f * PP;
    for (int i = tid; i < 128*56; i += 256) {
        int row = i / 56, c4 = i % 56;
        float4 v = *(float4*)&Cs[row*CSTR + c4*4];
        if (row < 64) {
            int l = l0 + row;
            if (l < KT) *(float4*)&g_Vre[(size_t)l*MPAD + fb + c4*4] = v;
        } else {
            int l = l0 + row - 64;
            if (l < KT) *(float4*)&g_Vim[(size_t)l*MPAD + fb + c4*4] = v;
        }
    }
}

// ---------------- fold: halve stage-2 K via l <-> KT-l symmetry ----------------
__global__ void k_fold() {
    int kap = blockIdx.x;
    int m = blockIdx.y*256 + threadIdx.x;
    float v;
    if (kap == 0)        v = g_Vre[m];
    else if (kap == 1)   v = g_Vre[(size_t)585*MPAD + m];
    else if (kap < 586) { int l = kap - 1;   v = g_Vre[(size_t)l*MPAD+m] + g_Vre[(size_t)(KT-l)*MPAD+m]; }
    else                { int l = kap - 585; v = g_Vim[(size_t)l*MPAD+m] - g_Vim[(size_t)(KT-l)*MPAD+m]; }
    g_Vf[(size_t)kap*MPAD + m] = v;
}

// ---------------- stage 2: wmma tf32 GEMM + fused clamp-power-partial-mean ----------------
// grid (2 qtiles, 210 mtiles), 256 threads (8 warps, 4M x 2N).
// Tile: M=128 (m), N=224 (q, masked at 390), K=1184 in 37 chunks of 32.
#define A2STR 136
#define B2STR 232

__global__ void __launch_bounds__(256)
k_s2mma() {
    __shared__ __align__(16) float As[32*A2STR];
    __shared__ __align__(16) float Bs[32*B2STR];
    __shared__ __align__(16) float Stg[8*256];

    int tid = threadIdx.x;
    int q0 = blockIdx.x * 224;
    int m0 = blockIdx.y * 128;
    int wid = tid >> 5, lane = tid & 31;
    int wm = wid & 3, wn = wid >> 2;
    int mb = wm * 32, nb = wn * 112;

    wmma::fragment<wmma::accumulator, 16, 16, 8, float> acc[2][7];
    #pragma unroll
    for (int mi = 0; mi < 2; mi++)
        #pragma unroll
        for (int ni = 0; ni < 7; ni++) wmma::fill_fragment(acc[mi][ni], 0.0f);

    for (int ch = 0; ch < 37; ch++) {
        int kb = ch*32;
        // A: 32 k-rows x 128 m  (As[k][m])
        #pragma unroll
        for (int e = 0; e < 4; e++) {
            int s = e*256 + tid;
            int row = s >> 5, off = s & 31;
            float4 v = *(const float4*)&g_Vf[(size_t)(kb+row)*MPAD + m0 + off*4];
            *(float4*)&As[row*A2STR + off*4] = v;
        }
        // B: 32 k-rows x 224 q  (Bs[k][q])
        for (int i = tid; i < 1792; i += 256) {
            int row = i / 56, c = i % 56;
            float4 v = *(const float4*)&g_E2f[(size_t)(kb+row)*NQPAD + q0 + c*4];
            *(float4*)&Bs[row*B2STR + c*4] = v;
        }
        __syncthreads();
        #pragma unroll
        for (int ks = 0; ks < 4; ks++) {
            wmma::fragment<wmma::matrix_a, 16, 16, 8, wmma::precision::tf32, wmma::col_major> a[2];
            wmma::fragment<wmma::matrix_b, 16, 16, 8, wmma::precision::tf32, wmma::row_major> b[7];
            #pragma unroll
            for (int mi = 0; mi < 2; mi++) {
                wmma::load_matrix_sync(a[mi], &As[(ks*8)*A2STR + mb + mi*16], A2STR);
                #pragma unroll
                for (int t = 0; t < a[mi].num_elements; t++)
                    a[mi].x[t] = wmma::__float_to_tf32(a[mi].x[t]);
            }
            #pragma unroll
            for (int ni = 0; ni < 7; ni++) {
                wmma::load_matrix_sync(b[ni], &Bs[(ks*8)*B2STR + nb + ni*16], B2STR);
                #pragma unroll
                for (int t = 0; t < b[ni].num_elements; t++)
                    b[ni].x[t] = wmma::__float_to_tf32(b[ni].x[t]);
            }
            #pragma unroll
            for (int mi = 0; mi < 2; mi++)
                #pragma unroll
                for (int ni = 0; ni < 7; ni++)
                    wmma::mma_sync(acc[mi][ni], a[mi], b[ni], acc[mi][ni]);
        }
        __syncthreads();
    }

    // ---- fused epilogue: per-warp staging, clamp-power row sums ----
    float* st = &Stg[wid*256];
    int r0 = lane >> 1, half = lane & 1;
    #pragma unroll
    for (int mi = 0; mi < 2; mi++) {
        float rs = 0.f;
        #pragma unroll
        for (int ni = 0; ni < 7; ni++) {
            wmma::store_matrix_sync(st, acc[mi][ni], 16, wmma::mem_row_major);
            __syncwarp();
            int qbase = q0 + nb + ni*16 + half*8;
            #pragma unroll
            for (int c = 0; c < 8; c++) {
                float v = st[r0*16 + half*8 + c];
                if (qbase + c < NTIME) rs += fmaxf(v*v, 1e-8f);
            }
            __syncwarp();
        }
        rs += __shfl_down_sync(0xffffffffu, rs, 1);
        int mrow = mb + mi*16 + r0;
        int m = m0 + mrow;
        int ff = m / PP, p = m - ff*PP;
        bool mok = (p < NFREQ) && (ff < NFILT);
        if (half == 0)
            g_Part[((blockIdx.y*2 + blockIdx.x)*2 + wn)*128 + mrow] = mok ? rs : 0.f;
    }
}

// ---------------- finalize ----------------
__global__ void k_fin(float* __restrict__ out) {
    int f = threadIdx.x;
    if (f >= NFILT) return;
    float s = 0.f;
    for (int p = 0; p < NFREQ; p++) {
        int m = f*PP + p;
        int mt = m >> 7, r = m & 127;
        #pragma unroll
        for (int sl = 0; sl < 4; sl++)
            s += g_Part[(mt*4 + sl)*128 + r];
    }
    out[f] = s * (1.0f / (float)(NFREQ*NTIME));
}

// ---------------- launch ----------------
extern "C" void kernel_launch(void* const* d_in, const int* in_sizes, int n_in,
                              void* d_out, int out_size) {
    (void)in_sizes; (void)n_in; (void)out_size;
    const float* x   = (const float*)d_in[0];
    const float* Hre = (const float*)d_in[1];
    const float* Him = (const float*)d_in[2];
    float* out = (float*)d_out;

    cudaFuncSetAttribute(k_s1mma, cudaFuncAttributeMaxDynamicSharedMemorySize, SM_TOT);

    k_tw    <<<5, 256>>>();
    k_B1    <<<(PP*KP + 255)/256, 256>>>();
    k_E2    <<<(KFOLD*NQPAD + 255)/256, 256>>>();
    k_P     <<<dim3(5, NFREQ), 256>>>(x);
    k_X     <<<dim3(5, KF),    256>>>();
    k_s1mma <<<dim3(LTILE, NFILT), 256, SM_TOT>>>(Hre, Him);
    k_fold  <<<dim3(KFOLD, NMT), 256>>>();
    k_s2mma <<<dim3(2, S2MT), 256>>>();
    k_fin   <<<1, 128>>>(out);
}

// round 11
// speedup vs baseline: 1.5757x; 1.5757x over previous
#include <cuda_runtime.h>
#include <cuda_fp16.h>
#include <mma.h>
#include <math.h>
#include <stdint.h>

using namespace nvcuda;

// Problem dims
#define NFREQ 211
#define NTIME 390
#define KF    422
#define KT    1170
#define NFILT 119
#define PP    224            // padded p stride per filter
#define MPAD  26880          // = 210*128 = 120*224
#define NMT   105            // fold m-tiles of 256
#define KFOLD 1170
#define K2P   1184           // stage-2 padded K (37*32)
#define NQPAD 448
#define KP    448            // stage-1 K' (S/iT interleaved)
#define NCHUNK 14            // stage-1 K' chunks of 32
#define LTILE 19             // l tiles of 64
#define S2MT  210            // stage-2 m-tiles of 128

#define ASCALE  0x1p-12f     // fp16 range guard on stage-1 A operand
#define PSCALE  0x1p24f      // undo (ASCALE^2) in the power epilogue

// ---------------- device scratch ----------------
__device__ float2 g_twP[KT];
__device__ float  g_t4c[KF], g_t4s[KF];
__device__ __align__(16) __half g_B1h[(size_t)PP*KP];      // stage-1 coeffs [p][k']
__device__ __align__(16) __half g_E2h[(size_t)K2P*NQPAD];  // rows >=1170 stay 0
__device__ float2 g_P[(size_t)NFREQ*KT];
__device__ float2 g_X[(size_t)KF*KT];
__device__ __align__(16) float g_Vre[(size_t)KT*MPAD];     // scaled by ASCALE
__device__ __align__(16) float g_Vim[(size_t)KT*MPAD];
__device__ __align__(16) float g_Vf [(size_t)K2P*MPAD];    // rows >=1170 stay 0
__device__ float  g_Part[S2MT*4*128];

// ---------------- helpers ----------------
__device__ __forceinline__ void ffma2(float2 &c, float2 a, float2 b) {
    unsigned long long uc = *reinterpret_cast<unsigned long long*>(&c);
    unsigned long long ua = *reinterpret_cast<unsigned long long*>(&a);
    unsigned long long ub = *reinterpret_cast<unsigned long long*>(&b);
    asm("fma.rn.f32x2 %0, %1, %2, %0;" : "+l"(uc) : "l"(ua), "l"(ub));
    c = *reinterpret_cast<float2*>(&uc);
}

// ---------------- builders ----------------
__global__ void k_tw() {
    int i = blockIdx.x*256 + threadIdx.x;
    if (i < KT) { double s,c; sincospi(2.0*i/KT, &s, &c); g_twP[i] = make_float2((float)c, (float)(-s)); }
    if (i < KF) { double s,c; sincospi(2.0*i/KF, &s, &c); g_t4c[i]=(float)c; g_t4s[i]=(float)s; }
}
__global__ void k_B1() {
    int i = blockIdx.x*256 + threadIdx.x;
    if (i >= PP*KP) return;
    int p = i / KP, k = i % KP;
    int kap = k >> 1; int iss = k & 1;
    double v = 0.0;
    const double inv = 1.0/(double)KF;
    if (p < NFREQ && kap <= 211) {
        if (kap == 0)        v = iss ? 0.0 : inv;
        else if (kap == 211) v = iss ? 0.0 : ((p & 1) ? -inv : inv);
        else {
            int r = (kap*p) % KF;
            double s,c; sincospi(2.0*r/KF, &s, &c);
            v = (iss ? s : c) * inv;
        }
    }
    g_B1h[i] = __float2half((float)v);
}
__global__ void k_E2() {
    int i = blockIdx.x*256 + threadIdx.x;
    if (i >= KFOLD*NQPAD) return;
    int kap = i / NQPAD, q = i % NQPAD;
    float val = 0.f;
    const float inv = 1.0f/(float)KT;
    if (q < NTIME) {
        if (kap == 0)      val = inv;
        else if (kap == 1) val = (q & 1) ? -inv : inv;
        else if (kap < 586) {
            int l = kap - 1;
            int r = (l*q) % KT;
            double s,c; sincospi(2.0*r/KT, &s, &c);
            val = (float)c * inv;
        } else {
            int l = kap - 585;
            int r = (l*q) % KT;
            double s,c; sincospi(2.0*r/KT, &s, &c);
            val = (float)(-s) * inv;
        }
    }
    g_E2h[(size_t)kap*NQPAD + q] = __float2half(val);
}

// ---------------- stage 0: X = fft2(pad(100*x)) -----------------
__global__ void k_P(const float* __restrict__ x) {
    __shared__ float2 tw[KT];
    __shared__ float  xs[NTIME];
    int tid = threadIdx.x;
    for (int i = tid; i < KT; i += 256) tw[i] = g_twP[i];
    int u = blockIdx.y;
    for (int i = tid; i < NTIME; i += 256) xs[i] = x[u*NTIME + i] * 100.0f;
    __syncthreads();
    int l = blockIdx.x*256 + tid;
    if (l >= KT) return;
    float2 acc = make_float2(0.f, 0.f);
    int j = 0;
    for (int v = 0; v < NTIME; v++) {
        float xv = xs[v];
        float2 x2 = make_float2(xv, xv);
        ffma2(acc, x2, tw[j]);
        j += l; if (j >= KT) j -= KT;
    }
    g_P[(size_t)u*KT + l] = acc;
}
__global__ void k_X() {
    __shared__ float sc[KF], ss[KF];
    int tid = threadIdx.x;
    for (int i = tid; i < KF; i += 256) { sc[i]=g_t4c[i]; ss[i]=g_t4s[i]; }
    __syncthreads();
    int l = blockIdx.x*256 + tid;
    int k = blockIdx.y;
    if (l >= KT) return;
    float2 acc = make_float2(0.f, 0.f);
    int j = 0;
    for (int u = 0; u < NFREQ; u++) {
        float2 P = g_P[(size_t)u*KT + l];
        float c = sc[j], s = ss[j];
        float2 c2 = make_float2(c, c), s2 = make_float2(s, s);
        float2 Pw = make_float2(P.y, -P.x);
        ffma2(acc, c2, P);
        ffma2(acc, s2, Pw);
        j += k; if (j >= KF) j -= KF;
    }
    g_X[(size_t)k*KT + l] = acc;
}

// ---------------- stage 1: wmma fp16 single-pass GEMM ----------------
// grid (LTILE, NFILT), 256 threads (8 warps, 4M x 2N).
// Tile: M=128 (rows 0-63: Re, 64-127: Im), N=224 (p), K'=448 in 14 chunks of 32.
#define ASTR 40
#define BSTR 40
#define CSTR 232
#define SM_A 0
#define SM_B 10240
#define SM_TOT 118784          // Cs (128*232*4) overlays A/B

__global__ void __launch_bounds__(256)
k_s1mma(const float* __restrict__ Hre, const float* __restrict__ Him) {
    extern __shared__ char smem[];
    __half* Ah = (__half*)(smem + SM_A);
    __half* Bh = (__half*)(smem + SM_B);
    float*  Cs = (float*)(smem);          // epilogue overlay

    int tid = threadIdx.x;
    int f  = blockIdx.y;
    int l0 = blockIdx.x * 64;

    int wid = tid >> 5;
    int wm = wid & 3, wn = wid >> 2;
    int mb = wm * 32, nb = wn * 112;

    wmma::fragment<wmma::accumulator, 16, 16, 16, float> acc[2][7];
    #pragma unroll
    for (int mi = 0; mi < 2; mi++)
        #pragma unroll
        for (int ni = 0; ni < 7; ni++) wmma::fill_fragment(acc[mi][ni], 0.0f);

    int lc = tid & 63;
    int kq = tid >> 6;
    int lg = l0 + lc;
    bool lok = (lg < KT);
    const size_t hb = (size_t)f * KF * KT;

    for (int ch = 0; ch < NCHUNK; ch++) {
        // ---- build A (fold of H*X, scaled): 16 kap x 64 l ----
        #pragma unroll
        for (int j = 0; j < 4; j++) {
            int ka = kq + j*4;
            int kg = ch*16 + ka;
            float Sx=0.f, Sy=0.f, iTx=0.f, iTy=0.f;
            if (lok && kg <= 211) {
                float2 X = g_X[(size_t)kg*KT + lg];
                float hr = Hre[hb + (size_t)kg*KT + lg];
                float hi = Him[hb + (size_t)kg*KT + lg];
                float war = hr*X.x - hi*X.y;
                float wai = hr*X.y + hi*X.x;
                if (kg >= 1 && kg <= 210) {
                    int km = KF - kg;
                    float2 X2 = g_X[(size_t)km*KT + lg];
                    float hr2 = Hre[hb + (size_t)km*KT + lg];
                    float hi2 = Him[hb + (size_t)km*KT + lg];
                    float wbr = hr2*X2.x - hi2*X2.y;
                    float wbi = hr2*X2.y + hi2*X2.x;
                    Sx = war + wbr; Sy = wai + wbi;
                    float Tx = war - wbr, Ty = wai - wbi;
                    iTx = -Ty; iTy = Tx;
                } else { Sx = war; Sy = wai; }
            }
            __half2 v0 = __floats2half2_rn(Sx*ASCALE, iTx*ASCALE);
            __half2 v1 = __floats2half2_rn(Sy*ASCALE, iTy*ASCALE);
            *(__half2*)&Ah[lc*ASTR + 2*ka]      = v0;
            *(__half2*)&Ah[(64+lc)*ASTR + 2*ka] = v1;
        }
        // ---- load B: 224 rows x 32 k' ----
        for (int i = tid; i < 896; i += 256) {
            int row = i >> 2, seg = i & 3;
            uint4 v = *(const uint4*)&g_B1h[(size_t)row*KP + ch*32 + seg*8];
            *(uint4*)&Bh[row*BSTR + seg*8] = v;
        }
        __syncthreads();

        #pragma unroll
        for (int ks = 0; ks < 2; ks++) {
            wmma::fragment<wmma::matrix_a, 16, 16, 16, __half, wmma::row_major> a[2];
            wmma::fragment<wmma::matrix_b, 16, 16, 16, __half, wmma::col_major> b[7];
            #pragma unroll
            for (int mi = 0; mi < 2; mi++)
                wmma::load_matrix_sync(a[mi], &Ah[(mb + mi*16)*ASTR + ks*16], ASTR);
            #pragma unroll
            for (int ni = 0; ni < 7; ni++)
                wmma::load_matrix_sync(b[ni], &Bh[(nb + ni*16)*BSTR + ks*16], BSTR);
            #pragma unroll
            for (int mi = 0; mi < 2; mi++)
                #pragma unroll
                for (int ni = 0; ni < 7; ni++)
                    wmma::mma_sync(acc[mi][ni], a[mi], b[ni], acc[mi][ni]);
        }
        __syncthreads();
    }

    // ---- epilogue: stage f32 to smem, coalesced f32 writes ----
    #pragma unroll
    for (int mi = 0; mi < 2; mi++)
        #pragma unroll
        for (int ni = 0; ni < 7; ni++)
            wmma::store_matrix_sync(&Cs[(mb + mi*16)*CSTR + nb + ni*16], acc[mi][ni],
                                    CSTR, wmma::mem_row_major);
    __syncthreads();

    size_t fb = (size_t)f * PP;
    for (int i = tid; i < 128*56; i += 256) {
        int row = i / 56, c4 = i % 56;
        float4 v = *(float4*)&Cs[row*CSTR + c4*4];
        if (row < 64) {
            int l = l0 + row;
            if (l < KT) *(float4*)&g_Vre[(size_t)l*MPAD + fb + c4*4] = v;
        } else {
            int l = l0 + row - 64;
            if (l < KT) *(float4*)&g_Vim[(size_t)l*MPAD + fb + c4*4] = v;
        }
    }
}

// ---------------- fold: halve stage-2 K via l <-> KT-l symmetry ----------------
__global__ void k_fold() {
    int kap = blockIdx.x;
    int m = blockIdx.y*256 + threadIdx.x;
    float v;
    if (kap == 0)        v = g_Vre[m];
    else if (kap == 1)   v = g_Vre[(size_t)585*MPAD + m];
    else if (kap < 586) { int l = kap - 1;   v = g_Vre[(size_t)l*MPAD+m] + g_Vre[(size_t)(KT-l)*MPAD+m]; }
    else                { int l = kap - 585; v = g_Vim[(size_t)l*MPAD+m] - g_Vim[(size_t)(KT-l)*MPAD+m]; }
    g_Vf[(size_t)kap*MPAD + m] = v;
}

// ---------------- stage 2: wmma fp16 GEMM + fused clamp-power-partial-mean ----------------
// grid (2 qtiles, 210 mtiles), 256 threads (8 warps, 4M x 2N).
// Tile: M=128 (m), N=224 (q, masked at 390), K=1184 in 37 chunks of 32.
#define A2STR 136
#define B2STR 232

__global__ void __launch_bounds__(256)
k_s2mma() {
    __shared__ __align__(16) __half As[32*A2STR];
    __shared__ __align__(16) __half Bs[32*B2STR];
    __shared__ __align__(16) float Stg[8*256];

    int tid = threadIdx.x;
    int q0 = blockIdx.x * 224;
    int m0 = blockIdx.y * 128;
    int wid = tid >> 5, lane = tid & 31;
    int wm = wid & 3, wn = wid >> 2;
    int mb = wm * 32, nb = wn * 112;

    wmma::fragment<wmma::accumulator, 16, 16, 16, float> acc[2][7];
    #pragma unroll
    for (int mi = 0; mi < 2; mi++)
        #pragma unroll
        for (int ni = 0; ni < 7; ni++) wmma::fill_fragment(acc[mi][ni], 0.0f);

    for (int ch = 0; ch < 37; ch++) {
        int kb = ch*32;
        // A: 32 k-rows x 128 m (convert f32 -> fp16 at load)
        #pragma unroll
        for (int e = 0; e < 2; e++) {
            int s = tid*2 + e;
            int row = s >> 4, off = s & 15;
            const float4* src = (const float4*)&g_Vf[(size_t)(kb+row)*MPAD + m0 + off*8];
            float4 v0 = src[0], v1 = src[1];
            __half2 h0 = __floats2half2_rn(v0.x, v0.y);
            __half2 h1 = __floats2half2_rn(v0.z, v0.w);
            __half2 h2 = __floats2half2_rn(v1.x, v1.y);
            __half2 h3 = __floats2half2_rn(v1.z, v1.w);
            uint4 pk;
            pk.x = *(uint32_t*)&h0; pk.y = *(uint32_t*)&h1;
            pk.z = *(uint32_t*)&h2; pk.w = *(uint32_t*)&h3;
            *(uint4*)&As[row*A2STR + off*8] = pk;
        }
        // B: 32 k-rows x 224 q
        for (int i = tid; i < 896; i += 256) {
            int row = i >> 5, c = i & 31;          // 32 rows x 28 segs... careful
            // 224 halves/row = 28 uint4; use div by 28
            row = i / 28; c = i % 28;
            uint4 v = *(const uint4*)&g_E2h[(size_t)(kb+row)*NQPAD + q0 + c*8];
            *(uint4*)&Bs[row*B2STR + c*8] = v;
        }
        __syncthreads();
        #pragma unroll
        for (int ks = 0; ks < 2; ks++) {
            wmma::fragment<wmma::matrix_a, 16, 16, 16, __half, wmma::col_major> a[2];
            wmma::fragment<wmma::matrix_b, 16, 16, 16, __half, wmma::row_major> b[7];
            #pragma unroll
            for (int mi = 0; mi < 2; mi++)
                wmma::load_matrix_sync(a[mi], &As[(ks*16)*A2STR + mb + mi*16], A2STR);
            #pragma unroll
            for (int ni = 0; ni < 7; ni++)
                wmma::load_matrix_sync(b[ni], &Bs[(ks*16)*B2STR + nb + ni*16], B2STR);
            #pragma unroll
            for (int mi = 0; mi < 2; mi++)
                #pragma unroll
                for (int ni = 0; ni < 7; ni++)
                    wmma::mma_sync(acc[mi][ni], a[mi], b[ni], acc[mi][ni]);
        }
        __syncthreads();
    }

    // ---- fused epilogue: per-warp staging, rescaled clamp-power row sums ----
    float* st = &Stg[wid*256];
    int r0 = lane >> 1, half = lane & 1;
    #pragma unroll
    for (int mi = 0; mi < 2; mi++) {
        float rs = 0.f;
        #pragma unroll
        for (int ni = 0; ni < 7; ni++) {
            wmma::store_matrix_sync(st, acc[mi][ni], 16, wmma::mem_row_major);
            __syncwarp();
            int qbase = q0 + nb + ni*16 + half*8;
            #pragma unroll
            for (int c = 0; c < 8; c++) {
                float v = st[r0*16 + half*8 + c];
                if (qbase + c < NTIME) rs += fmaxf(v*v*PSCALE, 1e-8f);
            }
            __syncwarp();
        }
        rs += __shfl_down_sync(0xffffffffu, rs, 1);
        int mrow = mb + mi*16 + r0;
        int m = m0 + mrow;
        int ff = m / PP, p = m - ff*PP;
        bool mok = (p < NFREQ) && (ff < NFILT);
        if (half == 0)
            g_Part[((blockIdx.y*2 + blockIdx.x)*2 + wn)*128 + mrow] = mok ? rs : 0.f;
    }
}

// ---------------- finalize ----------------
__global__ void k_fin(float* __restrict__ out) {
    int f = threadIdx.x;
    if (f >= NFILT) return;
    float s = 0.f;
    for (int p = 0; p < NFREQ; p++) {
        int m = f*PP + p;
        int mt = m >> 7, r = m & 127;
        #pragma unroll
        for (int sl = 0; sl < 4; sl++)
            s += g_Part[(mt*4 + sl)*128 + r];
    }
    out[f] = s * (1.0f / (float)(NFREQ*NTIME));
}

// ---------------- launch ----------------
extern "C" void kernel_launch(void* const* d_in, const int* in_sizes, int n_in,
                              void* d_out, int out_size) {
    (void)in_sizes; (void)n_in; (void)out_size;
    const float* x   = (const float*)d_in[0];
    const float* Hre = (const float*)d_in[1];
    const float* Him = (const float*)d_in[2];
    float* out = (float*)d_out;

    cudaFuncSetAttribute(k_s1mma, cudaFuncAttributeMaxDynamicSharedMemorySize, SM_TOT);

    k_tw    <<<5, 256>>>();
    k_B1    <<<(PP*KP + 255)/256, 256>>>();
    k_E2    <<<(KFOLD*NQPAD + 255)/256, 256>>>();
    k_P     <<<dim3(5, NFREQ), 256>>>(x);
    k_X     <<<dim3(5, KF),    256>>>();
    k_s1mma <<<dim3(LTILE, NFILT), 256, SM_TOT>>>(Hre, Him);
    k_fold  <<<dim3(KFOLD, NMT), 256>>>();
    k_s2mma <<<dim3(2, S2MT), 256>>>();
    k_fin   <<<1, 128>>>(out);
}

// round 12
// speedup vs baseline: 2.6766x; 1.6987x over previous
#include <cuda_runtime.h>
#include <cuda_fp16.h>
#include <mma.h>
#include <math.h>
#include <stdint.h>

using namespace nvcuda;

// Problem dims
#define NFREQ 211
#define NTIME 390
#define KF    422
#define KT    1170
#define NFILT 119
#define PP    224            // padded p stride per filter
#define MPAD  26880          // = 210*128 = 120*224
#define KFOLD 1170
#define K2P   1184           // stage-2 padded K (37*32)
#define NQPAD 448
#define KP    448            // stage-1 K' (S/iT interleaved)
#define NCHUNK 14            // stage-1 K' chunks of 32
#define S1LT  10             // stage-1 l tiles of 64 (640 >= 586 folded l values)
#define S2MT  210            // stage-2 m-tiles of 128

#define ASCALE  0x1p-12f     // fp16 range guard on stage-1 A operand
#define PSCALE  0x1p24f      // undo (ASCALE^2) in the power epilogue

// ---------------- device scratch ----------------
__device__ float2 g_twP[KT];
__device__ float  g_t4c[KF], g_t4s[KF];
__device__ __align__(16) __half g_B1h[(size_t)PP*KP];      // stage-1 coeffs [p][k']
__device__ __align__(16) __half g_E2h[(size_t)K2P*NQPAD];  // rows >=1170 stay 0
__device__ float2 g_P[(size_t)NFREQ*KT];
__device__ float2 g_X[(size_t)KF*KT];
__device__ __align__(16) __half g_Vf[(size_t)K2P*MPAD];    // folded V (scaled), rows >=1170 stay 0
__device__ float  g_Part[S2MT*4*128];

// ---------------- helpers ----------------
__device__ __forceinline__ void ffma2(float2 &c, float2 a, float2 b) {
    unsigned long long uc = *reinterpret_cast<unsigned long long*>(&c);
    unsigned long long ua = *reinterpret_cast<unsigned long long*>(&a);
    unsigned long long ub = *reinterpret_cast<unsigned long long*>(&b);
    asm("fma.rn.f32x2 %0, %1, %2, %0;" : "+l"(uc) : "l"(ua), "l"(ub));
    c = *reinterpret_cast<float2*>(&uc);
}

// ---------------- builders ----------------
__global__ void k_tw() {
    int i = blockIdx.x*256 + threadIdx.x;
    if (i < KT) { double s,c; sincospi(2.0*i/KT, &s, &c); g_twP[i] = make_float2((float)c, (float)(-s)); }
    if (i < KF) { double s,c; sincospi(2.0*i/KF, &s, &c); g_t4c[i]=(float)c; g_t4s[i]=(float)s; }
}
__global__ void k_B1() {
    int i = blockIdx.x*256 + threadIdx.x;
    if (i >= PP*KP) return;
    int p = i / KP, k = i % KP;
    int kap = k >> 1; int iss = k & 1;
    double v = 0.0;
    const double inv = 1.0/(double)KF;
    if (p < NFREQ && kap <= 211) {
        if (kap == 0)        v = iss ? 0.0 : inv;
        else if (kap == 211) v = iss ? 0.0 : ((p & 1) ? -inv : inv);
        else {
            int r = (kap*p) % KF;
            double s,c; sincospi(2.0*r/KF, &s, &c);
            v = (iss ? s : c) * inv;
        }
    }
    g_B1h[i] = __float2half((float)v);
}
__global__ void k_E2() {
    int i = blockIdx.x*256 + threadIdx.x;
    if (i >= KFOLD*NQPAD) return;
    int kap = i / NQPAD, q = i % NQPAD;
    float val = 0.f;
    const float inv = 1.0f/(float)KT;
    if (q < NTIME) {
        if (kap == 0)      val = inv;
        else if (kap == 1) val = (q & 1) ? -inv : inv;
        else if (kap < 586) {
            int l = kap - 1;
            int r = (l*q) % KT;
            double s,c; sincospi(2.0*r/KT, &s, &c);
            val = (float)c * inv;
        } else {
            int l = kap - 585;
            int r = (l*q) % KT;
            double s,c; sincospi(2.0*r/KT, &s, &c);
            val = (float)(-s) * inv;
        }
    }
    g_E2h[(size_t)kap*NQPAD + q] = __float2half(val);
}

// ---------------- stage 0: X = fft2(pad(100*x)) -----------------
__global__ void k_P(const float* __restrict__ x) {
    __shared__ float2 tw[KT];
    __shared__ float  xs[NTIME];
    int tid = threadIdx.x;
    for (int i = tid; i < KT; i += 256) tw[i] = g_twP[i];
    int u = blockIdx.y;
    for (int i = tid; i < NTIME; i += 256) xs[i] = x[u*NTIME + i] * 100.0f;
    __syncthreads();
    int l = blockIdx.x*256 + tid;
    if (l >= KT) return;
    float2 acc = make_float2(0.f, 0.f);
    int j = 0;
    for (int v = 0; v < NTIME; v++) {
        float xv = xs[v];
        float2 x2 = make_float2(xv, xv);
        ffma2(acc, x2, tw[j]);
        j += l; if (j >= KT) j -= KT;
    }
    g_P[(size_t)u*KT + l] = acc;
}
__global__ void k_X() {
    __shared__ float sc[KF], ss[KF];
    int tid = threadIdx.x;
    for (int i = tid; i < KF; i += 256) { sc[i]=g_t4c[i]; ss[i]=g_t4s[i]; }
    __syncthreads();
    int l = blockIdx.x*256 + tid;
    int k = blockIdx.y;
    if (l >= KT) return;
    float2 acc = make_float2(0.f, 0.f);
    int j = 0;
    for (int u = 0; u < NFREQ; u++) {
        float2 P = g_P[(size_t)u*KT + l];
        float c = sc[j], s = ss[j];
        float2 c2 = make_float2(c, c), s2 = make_float2(s, s);
        float2 Pw = make_float2(P.y, -P.x);
        ffma2(acc, c2, P);
        ffma2(acc, s2, Pw);
        j += k; if (j >= KF) j -= KF;
    }
    g_X[(size_t)k*KT + l] = acc;
}

// freq-fold of H*X at (kap kg, time lg): A_re=(Sx,iTx) -> Vre, A_im=(Sy,iTy) -> Vim
__device__ __forceinline__ void foldA(const float* __restrict__ Hre, const float* __restrict__ Him,
                                      size_t hb, int kg, int lg,
                                      float &Sx, float &Sy, float &iTx, float &iTy) {
    Sx = Sy = iTx = iTy = 0.f;
    if (kg <= 211) {
        float2 X = g_X[(size_t)kg*KT + lg];
        float hr = Hre[hb + (size_t)kg*KT + lg];
        float hi = Him[hb + (size_t)kg*KT + lg];
        float war = hr*X.x - hi*X.y;
        float wai = hr*X.y + hi*X.x;
        if (kg >= 1 && kg <= 210) {
            int km = KF - kg;
            float2 X2 = g_X[(size_t)km*KT + lg];
            float hr2 = Hre[hb + (size_t)km*KT + lg];
            float hi2 = Him[hb + (size_t)km*KT + lg];
            float wbr = hr2*X2.x - hi2*X2.y;
            float wbi = hr2*X2.y + hi2*X2.x;
            Sx = war + wbr; Sy = wai + wbi;
            float Tx = war - wbr, Ty = wai - wbi;
            iTx = -Ty; iTy = Tx;
        } else { Sx = war; Sy = wai; }
    }
}

// ---------------- stage 1: wmma fp16 GEMM with time-fold fused into A ----------------
// grid (S1LT, NFILT), 256 threads (8 warps, 4M x 2N).
// Tile: M=128 (rows 0-63: cos rows for l0+i, 64-127: sin rows), N=224 (p), K'=448.
// Emits folded Vf (fp16, scaled) directly; no separate V / fold pass.
#define ASTR 40
#define BSTR 40
#define CSTR 232
#define SM_A 0
#define SM_B 10240
#define SM_TOT 118784          // Cs (128*232*4) overlays A/B

__global__ void __launch_bounds__(256)
k_s1mma(const float* __restrict__ Hre, const float* __restrict__ Him) {
    extern __shared__ char smem[];
    __half* Ah = (__half*)(smem + SM_A);
    __half* Bh = (__half*)(smem + SM_B);
    float*  Cs = (float*)(smem);          // epilogue overlay

    int tid = threadIdx.x;
    int f  = blockIdx.y;
    int l0 = blockIdx.x * 64;

    int wid = tid >> 5;
    int wm = wid & 3, wn = wid >> 2;
    int mb = wm * 32, nb = wn * 112;

    wmma::fragment<wmma::accumulator, 16, 16, 16, float> acc[2][7];
    #pragma unroll
    for (int mi = 0; mi < 2; mi++)
        #pragma unroll
        for (int ni = 0; ni < 7; ni++) wmma::fill_fragment(acc[mi][ni], 0.0f);

    int lc = tid & 63;
    int kq = tid >> 6;
    int lg  = l0 + lc;                      // 0..639 < KT
    int lmg = (lg == 0) ? 0 : KT - lg;      // time mirror
    float fm = (lg >= 1 && lg <= 584) ? 1.0f : 0.0f;   // mirror distinct & in range
    const size_t hb = (size_t)f * KF * KT;

    for (int ch = 0; ch < NCHUNK; ch++) {
        // ---- build folded A: 16 kap x 64 l-pairs ----
        #pragma unroll
        for (int j = 0; j < 4; j++) {
            int ka = kq + j*4;
            int kg = ch*16 + ka;
            float S1x,S1y,iT1x,iT1y, S2x,S2y,iT2x,iT2y;
            foldA(Hre, Him, hb, kg, lg,  S1x, S1y, iT1x, iT1y);
            foldA(Hre, Him, hb, kg, lmg, S2x, S2y, iT2x, iT2y);
            // cos row (-> Vre[l]+Vre[KT-l]); sin row (-> Vim[l]-Vim[KT-l])
            float cx = S1x + fm*S2x,  cz = iT1x + fm*iT2x;
            float sx = S1y - fm*S2y,  sz = iT1y - fm*iT2y;
            *(__half2*)&Ah[lc*ASTR + 2*ka]      = __floats2half2_rn(cx*ASCALE, cz*ASCALE);
            *(__half2*)&Ah[(64+lc)*ASTR + 2*ka] = __floats2half2_rn(sx*ASCALE, sz*ASCALE);
        }
        // ---- load B: 224 rows x 32 k' ----
        for (int i = tid; i < 896; i += 256) {
            int row = i >> 2, seg = i & 3;
            uint4 v = *(const uint4*)&g_B1h[(size_t)row*KP + ch*32 + seg*8];
            *(uint4*)&Bh[row*BSTR + seg*8] = v;
        }
        __syncthreads();

        #pragma unroll
        for (int ks = 0; ks < 2; ks++) {
            wmma::fragment<wmma::matrix_a, 16, 16, 16, __half, wmma::row_major> a[2];
            wmma::fragment<wmma::matrix_b, 16, 16, 16, __half, wmma::col_major> b[7];
            #pragma unroll
            for (int mi = 0; mi < 2; mi++)
                wmma::load_matrix_sync(a[mi], &Ah[(mb + mi*16)*ASTR + ks*16], ASTR);
            #pragma unroll
            for (int ni = 0; ni < 7; ni++)
                wmma::load_matrix_sync(b[ni], &Bh[(nb + ni*16)*BSTR + ks*16], BSTR);
            #pragma unroll
            for (int mi = 0; mi < 2; mi++)
                #pragma unroll
                for (int ni = 0; ni < 7; ni++)
                    wmma::mma_sync(acc[mi][ni], a[mi], b[ni], acc[mi][ni]);
        }
        __syncthreads();
    }

    // ---- epilogue: stage f32 to smem, convert fp16, scatter rows to Vf ----
    #pragma unroll
    for (int mi = 0; mi < 2; mi++)
        #pragma unroll
        for (int ni = 0; ni < 7; ni++)
            wmma::store_matrix_sync(&Cs[(mb + mi*16)*CSTR + nb + ni*16], acc[mi][ni],
                                    CSTR, wmma::mem_row_major);
    __syncthreads();

    size_t fb = (size_t)f * PP;
    for (int i = tid; i < 128*28; i += 256) {
        int row = i / 28, c8 = i % 28;
        int l, t;
        if (row < 64) {
            l = l0 + row;
            t = (l == 0) ? 0 : (l == 585) ? 1 : (l >= 1 && l <= 584) ? l + 1 : -1;
        } else {
            l = l0 + row - 64;
            t = (l >= 1 && l <= 584) ? 585 + l : -1;
        }
        if (t >= 0) {
            const float4* src = (const float4*)&Cs[row*CSTR + c8*8];
            float4 v0 = src[0], v1 = src[1];
            __half2 h0 = __floats2half2_rn(v0.x, v0.y);
            __half2 h1 = __floats2half2_rn(v0.z, v0.w);
            __half2 h2 = __floats2half2_rn(v1.x, v1.y);
            __half2 h3 = __floats2half2_rn(v1.z, v1.w);
            uint4 pk;
            pk.x = *(uint32_t*)&h0; pk.y = *(uint32_t*)&h1;
            pk.z = *(uint32_t*)&h2; pk.w = *(uint32_t*)&h3;
            *(uint4*)&g_Vf[(size_t)t*MPAD + fb + c8*8] = pk;
        }
    }
}

// ---------------- stage 2: wmma fp16 GEMM + fused clamp-power-partial-mean ----------------
// grid (2 qtiles, 210 mtiles), 256 threads (8 warps, 4M x 2N).
// Tile: M=128 (m), N=224 (q, masked at 390), K=1184 in 37 chunks of 32.
#define A2STR 136
#define B2STR 232

__global__ void __launch_bounds__(256)
k_s2mma() {
    __shared__ __align__(16) __half As[32*A2STR];
    __shared__ __align__(16) __half Bs[32*B2STR];
    __shared__ __align__(16) float Stg[8*256];

    int tid = threadIdx.x;
    int q0 = blockIdx.x * 224;
    int m0 = blockIdx.y * 128;
    int wid = tid >> 5, lane = tid & 31;
    int wm = wid & 3, wn = wid >> 2;
    int mb = wm * 32, nb = wn * 112;

    wmma::fragment<wmma::accumulator, 16, 16, 16, float> acc[2][7];
    #pragma unroll
    for (int mi = 0; mi < 2; mi++)
        #pragma unroll
        for (int ni = 0; ni < 7; ni++) wmma::fill_fragment(acc[mi][ni], 0.0f);

    for (int ch = 0; ch < 37; ch++) {
        int kb = ch*32;
        // A: 32 k-rows x 128 m (fp16 direct copy)
        #pragma unroll
        for (int e = 0; e < 2; e++) {
            int s = tid*2 + e;
            int row = s >> 4, off = s & 15;
            uint4 v = *(const uint4*)&g_Vf[(size_t)(kb+row)*MPAD + m0 + off*8];
            *(uint4*)&As[row*A2STR + off*8] = v;
        }
        // B: 32 k-rows x 224 q
        for (int i = tid; i < 896; i += 256) {
            int row = i / 28, c = i % 28;
            uint4 v = *(const uint4*)&g_E2h[(size_t)(kb+row)*NQPAD + q0 + c*8];
            *(uint4*)&Bs[row*B2STR + c*8] = v;
        }
        __syncthreads();
        #pragma unroll
        for (int ks = 0; ks < 2; ks++) {
            wmma::fragment<wmma::matrix_a, 16, 16, 16, __half, wmma::col_major> a[2];
            wmma::fragment<wmma::matrix_b, 16, 16, 16, __half, wmma::row_major> b[7];
            #pragma unroll
            for (int mi = 0; mi < 2; mi++)
                wmma::load_matrix_sync(a[mi], &As[(ks*16)*A2STR + mb + mi*16], A2STR);
            #pragma unroll
            for (int ni = 0; ni < 7; ni++)
                wmma::load_matrix_sync(b[ni], &Bs[(ks*16)*B2STR + nb + ni*16], B2STR);
            #pragma unroll
            for (int mi = 0; mi < 2; mi++)
                #pragma unroll
                for (int ni = 0; ni < 7; ni++)
                    wmma::mma_sync(acc[mi][ni], a[mi], b[ni], acc[mi][ni]);
        }
        __syncthreads();
    }

    // ---- fused epilogue: per-warp staging, rescaled clamp-power row sums ----
    float* st = &Stg[wid*256];
    int r0 = lane >> 1, half = lane & 1;
    #pragma unroll
    for (int mi = 0; mi < 2; mi++) {
        float rs = 0.f;
        #pragma unroll
        for (int ni = 0; ni < 7; ni++) {
            wmma::store_matrix_sync(st, acc[mi][ni], 16, wmma::mem_row_major);
            __syncwarp();
            int qbase = q0 + nb + ni*16 + half*8;
            #pragma unroll
            for (int c = 0; c < 8; c++) {
                float v = st[r0*16 + half*8 + c];
                if (qbase + c < NTIME) rs += fmaxf(v*v*PSCALE, 1e-8f);
            }
            __syncwarp();
        }
        rs += __shfl_down_sync(0xffffffffu, rs, 1);
        int mrow = mb + mi*16 + r0;
        int m = m0 + mrow;
        int ff = m / PP, p = m - ff*PP;
        bool mok = (p < NFREQ) && (ff < NFILT);
        if (half == 0)
            g_Part[((blockIdx.y*2 + blockIdx.x)*2 + wn)*128 + mrow] = mok ? rs : 0.f;
    }
}

// ---------------- finalize ----------------
__global__ void k_fin(float* __restrict__ out) {
    int f = threadIdx.x;
    if (f >= NFILT) return;
    float s = 0.f;
    for (int p = 0; p < NFREQ; p++) {
        int m = f*PP + p;
        int mt = m >> 7, r = m & 127;
        #pragma unroll
        for (int sl = 0; sl < 4; sl++)
            s += g_Part[(mt*4 + sl)*128 + r];
    }
    out[f] = s * (1.0f / (float)(NFREQ*NTIME));
}

// ---------------- launch ----------------
extern "C" void kernel_launch(void* const* d_in, const int* in_sizes, int n_in,
                              void* d_out, int out_size) {
    (void)in_sizes; (void)n_in; (void)out_size;
    const float* x   = (const float*)d_in[0];
    const float* Hre = (const float*)d_in[1];
    const float* Him = (const float*)d_in[2];
    float* out = (float*)d_out;

    cudaFuncSetAttribute(k_s1mma, cudaFuncAttributeMaxDynamicSharedMemorySize, SM_TOT);

    k_tw    <<<5, 256>>>();
    k_B1    <<<(PP*KP + 255)/256, 256>>>();
    k_E2    <<<(KFOLD*NQPAD + 255)/256, 256>>>();
    k_P     <<<dim3(5, NFREQ), 256>>>(x);
    k_X     <<<dim3(5, KF),    256>>>();
    k_s1mma <<<dim3(S1LT, NFILT), 256, SM_TOT>>>(Hre, Him);
    k_s2mma <<<dim3(2, S2MT), 256>>>();
    k_fin   <<<1, 128>>>(out);
}

// round 13
// speedup vs baseline: 3.3991x; 1.2699x over previous
#include <cuda_runtime.h>
#include <cuda_fp16.h>
#include <mma.h>
#include <math.h>
#include <stdint.h>

using namespace nvcuda;

// Problem dims
#define NFREQ 211
#define NTIME 390
#define KF    422
#define KT    1170
#define NFILT 119
#define PP    224            // padded p stride per filter
#define MPAD  26880          // = 210*128 = 120*224
#define KFOLD 1170
#define K2P   1184           // stage-2 padded K (37*32)
#define NQPAD 448
#define KP    448            // stage-1 K' (S/iT interleaved)
#define NCHUNK 14            // stage-1 K' chunks of 32
#define S1LT  10             // stage-1 l tiles of 64
#define S2MT  210            // stage-2 m-tiles of 128

#define ASCALE  0x1p-12f     // fp16 range guard on stage-1 A operand
#define PSCALE  0x1p24f      // undo (ASCALE^2) in the power epilogue

// ---------------- device scratch ----------------
__device__ __align__(16) __half g_B1h[(size_t)PP*KP];      // stage-1 coeffs [p][k']
__device__ __align__(16) __half g_E2h[(size_t)K2P*NQPAD];  // rows >=1170 stay 0
__device__ float2 g_P[(size_t)NFREQ*KT];
__device__ float2 g_X[(size_t)KF*KT];
__device__ __align__(16) __half g_Vf[(size_t)K2P*MPAD];    // folded V (scaled), rows >=1170 stay 0
__device__ float  g_Part[S2MT*4*128];

// ---------------- builders (f32 trig: outputs get fp16-rounded anyway) ----------------
__global__ void k_B1() {
    int i = blockIdx.x*256 + threadIdx.x;
    if (i >= PP*KP) return;
    int p = i / KP, k = i % KP;
    int kap = k >> 1; int iss = k & 1;
    float v = 0.f;
    const float inv = 1.0f/(float)KF;
    if (p < NFREQ && kap <= 211) {
        if (kap == 0)        v = iss ? 0.f : inv;
        else if (kap == 211) v = iss ? 0.f : ((p & 1) ? -inv : inv);
        else {
            int r = (kap*p) % KF;
            float s, c; sincospif(2.0f*(float)r/(float)KF, &s, &c);
            v = (iss ? s : c) * inv;
        }
    }
    g_B1h[i] = __float2half(v);
}
__global__ void k_E2() {
    int i = blockIdx.x*256 + threadIdx.x;
    if (i >= KFOLD*NQPAD) return;
    int kap = i / NQPAD, q = i % NQPAD;
    float val = 0.f;
    const float inv = 1.0f/(float)KT;
    if (q < NTIME) {
        if (kap == 0)      val = inv;
        else if (kap == 1) val = (q & 1) ? -inv : inv;
        else if (kap < 586) {
            int l = kap - 1;
            int r = (l*q) % KT;
            float s, c; sincospif(2.0f*(float)r/(float)KT, &s, &c);
            val = c * inv;
        } else {
            int l = kap - 585;
            int r = (l*q) % KT;
            float s, c; sincospif(2.0f*(float)r/(float)KT, &s, &c);
            val = -s * inv;
        }
    }
    g_E2h[(size_t)kap*NQPAD + q] = __float2half(val);
}

// ---------------- stage 0: X = fft2(pad(100*x)), rotation-recurrence DFT ----------------
__global__ void k_P(const float* __restrict__ x) {
    __shared__ float xs[NTIME];
    int tid = threadIdx.x;
    int u = blockIdx.y;
    for (int i = tid; i < NTIME; i += 256) xs[i] = x[u*NTIME + i] * 100.0f;
    __syncthreads();
    int l = blockIdx.x*256 + tid;
    if (l >= KT) return;
    double sd, cd; sincospi(-2.0*l/KT, &sd, &cd);
    float wr = (float)cd, wi = (float)sd;
    float tr = 1.f, ti = 0.f;
    float ar = 0.f, ai = 0.f;
    #pragma unroll 2
    for (int v = 0; v < NTIME; v++) {
        float xv = xs[v];
        ar = fmaf(xv, tr, ar);
        ai = fmaf(xv, ti, ai);
        float nr = fmaf(tr, wr, -ti*wi);
        float ni = fmaf(tr, wi,  ti*wr);
        tr = nr; ti = ni;
    }
    g_P[(size_t)u*KT + l] = make_float2(ar, ai);
}
__global__ void k_X() {
    int tid = threadIdx.x;
    int l = blockIdx.x*256 + tid;
    int k = blockIdx.y;
    if (l >= KT) return;
    double sd, cd; sincospi(-2.0*k/KF, &sd, &cd);
    float wr = (float)cd, wi = (float)sd;
    float tr = 1.f, ti = 0.f;
    float xr = 0.f, xi = 0.f;
    #pragma unroll 2
    for (int u = 0; u < NFREQ; u++) {
        float2 P = g_P[(size_t)u*KT + l];
        xr += P.x*tr - P.y*ti;
        xi += P.x*ti + P.y*tr;
        float nr = fmaf(tr, wr, -ti*wi);
        float ni = fmaf(tr, wi,  ti*wr);
        tr = nr; ti = ni;
    }
    g_X[(size_t)k*KT + l] = make_float2(xr, xi);
}

// freq-fold of H*X at (kap kg, time lg)
__device__ __forceinline__ void foldA(const float* __restrict__ Hre, const float* __restrict__ Him,
                                      size_t hb, int kg, int lg,
                                      float &Sx, float &Sy, float &iTx, float &iTy) {
    Sx = Sy = iTx = iTy = 0.f;
    if (kg <= 211) {
        float2 X = g_X[(size_t)kg*KT + lg];
        float hr = Hre[hb + (size_t)kg*KT + lg];
        float hi = Him[hb + (size_t)kg*KT + lg];
        float war = hr*X.x - hi*X.y;
        float wai = hr*X.y + hi*X.x;
        if (kg >= 1 && kg <= 210) {
            int km = KF - kg;
            float2 X2 = g_X[(size_t)km*KT + lg];
            float hr2 = Hre[hb + (size_t)km*KT + lg];
            float hi2 = Him[hb + (size_t)km*KT + lg];
            float wbr = hr2*X2.x - hi2*X2.y;
            float wbi = hr2*X2.y + hi2*X2.x;
            Sx = war + wbr; Sy = wai + wbi;
            float Tx = war - wbr, Ty = wai - wbi;
            iTx = -Ty; iTy = Tx;
        } else { Sx = war; Sy = wai; }
    }
}

// ---------------- stage 1: fp16 WMMA GEMM, time-fold fused into A ----------------
// grid (S1LT, NFILT), 512 threads (16 warps: 8M x 2N, acc[7] per warp).
// Tile: M=128 (rows 0-63: cos rows, 64-127: sin rows), N=224 (p), K'=448.
#define ASTR 40
#define BSTR 40
#define CSTR 232
#define SM_A 0
#define SM_B 10240
#define SM_TOT 59392           // Cs 64 rows (two-phase epilogue) overlays A/B

__global__ void __launch_bounds__(512)
k_s1mma(const float* __restrict__ Hre, const float* __restrict__ Him) {
    extern __shared__ char smem[];
    __half* Ah = (__half*)(smem + SM_A);
    __half* Bh = (__half*)(smem + SM_B);
    float*  Cs = (float*)(smem);          // epilogue overlay (64 x CSTR)

    int tid = threadIdx.x;
    int f  = blockIdx.y;
    int l0 = blockIdx.x * 64;

    int wid = tid >> 5;
    int wm = wid & 7, wn = wid >> 3;
    int mb = wm * 16, nb = wn * 112;

    wmma::fragment<wmma::accumulator, 16, 16, 16, float> acc[7];
    #pragma unroll
    for (int ni = 0; ni < 7; ni++) wmma::fill_fragment(acc[ni], 0.0f);

    int lc = tid & 63;
    int kq = tid >> 6;                      // 0..7
    int lg  = l0 + lc;                      // 0..639 < KT
    int lmg = (lg == 0) ? 0 : KT - lg;      // time mirror
    float fm = (lg >= 1 && lg <= 584) ? 1.0f : 0.0f;
    const size_t hb = (size_t)f * KF * KT;

    for (int ch = 0; ch < NCHUNK; ch++) {
        // ---- build folded A: 16 kap x 64 l-pairs ----
        #pragma unroll
        for (int j = 0; j < 2; j++) {
            int ka = kq + j*8;
            int kg = ch*16 + ka;
            float S1x,S1y,iT1x,iT1y, S2x,S2y,iT2x,iT2y;
            foldA(Hre, Him, hb, kg, lg,  S1x, S1y, iT1x, iT1y);
            foldA(Hre, Him, hb, kg, lmg, S2x, S2y, iT2x, iT2y);
            float cx = S1x + fm*S2x,  cz = iT1x + fm*iT2x;
            float sx = S1y - fm*S2y,  sz = iT1y - fm*iT2y;
            *(__half2*)&Ah[lc*ASTR + 2*ka]      = __floats2half2_rn(cx*ASCALE, cz*ASCALE);
            *(__half2*)&Ah[(64+lc)*ASTR + 2*ka] = __floats2half2_rn(sx*ASCALE, sz*ASCALE);
        }
        // ---- load B: 224 rows x 32 k' ----
        for (int i = tid; i < 896; i += 512) {
            int row = i >> 2, seg = i & 3;
            uint4 v = *(const uint4*)&g_B1h[(size_t)row*KP + ch*32 + seg*8];
            *(uint4*)&Bh[row*BSTR + seg*8] = v;
        }
        __syncthreads();

        #pragma unroll
        for (int ks = 0; ks < 2; ks++) {
            wmma::fragment<wmma::matrix_a, 16, 16, 16, __half, wmma::row_major> a;
            wmma::load_matrix_sync(a, &Ah[mb*ASTR + ks*16], ASTR);
            #pragma unroll
            for (int ni = 0; ni < 7; ni++) {
                wmma::fragment<wmma::matrix_b, 16, 16, 16, __half, wmma::col_major> b;
                wmma::load_matrix_sync(b, &Bh[(nb + ni*16)*BSTR + ks*16], BSTR);
                wmma::mma_sync(acc[ni], a, b, acc[ni]);
            }
        }
        __syncthreads();
    }

    // ---- two-phase epilogue: 64 rows at a time ----
    size_t fb = (size_t)f * PP;
    #pragma unroll
    for (int p = 0; p < 2; p++) {
        if ((wm >> 2) == p) {
            #pragma unroll
            for (int ni = 0; ni < 7; ni++)
                wmma::store_matrix_sync(&Cs[((wm & 3)*16)*CSTR + nb + ni*16], acc[ni],
                                        CSTR, wmma::mem_row_major);
        }
        __syncthreads();
        for (int i = tid; i < 64*28; i += 512) {
            int row = i / 28, c8 = i % 28;
            int l = l0 + row;
            int t;
            if (p == 0) t = (l == 0) ? 0 : (l == 585) ? 1 : (l >= 1 && l <= 584) ? l + 1 : -1;
            else        t = (l >= 1 && l <= 584) ? 585 + l : -1;
            if (t >= 0) {
                const float4* src = (const float4*)&Cs[row*CSTR + c8*8];
                float4 v0 = src[0], v1 = src[1];
                __half2 h0 = __floats2half2_rn(v0.x, v0.y);
                __half2 h1 = __floats2half2_rn(v0.z, v0.w);
                __half2 h2 = __floats2half2_rn(v1.x, v1.y);
                __half2 h3 = __floats2half2_rn(v1.z, v1.w);
                uint4 pk;
                pk.x = *(uint32_t*)&h0; pk.y = *(uint32_t*)&h1;
                pk.z = *(uint32_t*)&h2; pk.w = *(uint32_t*)&h3;
                *(uint4*)&g_Vf[(size_t)t*MPAD + fb + c8*8] = pk;
            }
        }
        __syncthreads();
    }
}

// ---------------- stage 2: fp16 WMMA GEMM + fused clamp-power-partial-mean ----------------
// grid (2 qtiles, 210 mtiles), 512 threads (16 warps: 8M x 2N, acc[7] per warp).
// Tile: M=128 (m), N=224 (q, masked at 390), K=1184 in 37 chunks of 32.
#define A2STR 136
#define B2STR 232

__global__ void __launch_bounds__(512)
k_s2mma() {
    __shared__ __align__(16) __half As[32*A2STR];
    __shared__ __align__(16) __half Bs[32*B2STR];
    __shared__ __align__(16) float Stg[16*256];

    int tid = threadIdx.x;
    int q0 = blockIdx.x * 224;
    int m0 = blockIdx.y * 128;
    int wid = tid >> 5, lane = tid & 31;
    int wm = wid & 7, wn = wid >> 3;
    int mb = wm * 16, nb = wn * 112;

    wmma::fragment<wmma::accumulator, 16, 16, 16, float> acc[7];
    #pragma unroll
    for (int ni = 0; ni < 7; ni++) wmma::fill_fragment(acc[ni], 0.0f);

    for (int ch = 0; ch < 37; ch++) {
        int kb = ch*32;
        // A: 32 k-rows x 128 m (fp16 direct copy, 1 uint4 per thread)
        {
            int row = tid >> 4, off = tid & 15;
            uint4 v = *(const uint4*)&g_Vf[(size_t)(kb+row)*MPAD + m0 + off*8];
            *(uint4*)&As[row*A2STR + off*8] = v;
        }
        // B: 32 k-rows x 224 q
        for (int i = tid; i < 896; i += 512) {
            int row = i / 28, c = i % 28;
            uint4 v = *(const uint4*)&g_E2h[(size_t)(kb+row)*NQPAD + q0 + c*8];
            *(uint4*)&Bs[row*B2STR + c*8] = v;
        }
        __syncthreads();
        #pragma unroll
        for (int ks = 0; ks < 2; ks++) {
            wmma::fragment<wmma::matrix_a, 16, 16, 16, __half, wmma::col_major> a;
            wmma::load_matrix_sync(a, &As[(ks*16)*A2STR + mb], A2STR);
            #pragma unroll
            for (int ni = 0; ni < 7; ni++) {
                wmma::fragment<wmma::matrix_b, 16, 16, 16, __half, wmma::row_major> b;
                wmma::load_matrix_sync(b, &Bs[(ks*16)*B2STR + nb + ni*16], B2STR);
                wmma::mma_sync(acc[ni], a, b, acc[ni]);
            }
        }
        __syncthreads();
    }

    // ---- fused epilogue: per-warp staging, rescaled clamp-power row sums ----
    float* st = &Stg[wid*256];
    int r0 = lane >> 1, half = lane & 1;
    float rs = 0.f;
    #pragma unroll
    for (int ni = 0; ni < 7; ni++) {
        wmma::store_matrix_sync(st, acc[ni], 16, wmma::mem_row_major);
        __syncwarp();
        int qbase = q0 + nb + ni*16 + half*8;
        #pragma unroll
        for (int c = 0; c < 8; c++) {
            float v = st[r0*16 + half*8 + c];
            if (qbase + c < NTIME) rs += fmaxf(v*v*PSCALE, 1e-8f);
        }
        __syncwarp();
    }
    rs += __shfl_down_sync(0xffffffffu, rs, 1);
    int mrow = mb + r0;
    int m = m0 + mrow;
    int ff = m / PP, p = m - ff*PP;
    bool mok = (p < NFREQ) && (ff < NFILT);
    if (half == 0)
        g_Part[((blockIdx.y*2 + blockIdx.x)*2 + wn)*128 + mrow] = mok ? rs : 0.f;
}

// ---------------- finalize ----------------
__global__ void k_fin(float* __restrict__ out) {
    int f = threadIdx.x;
    if (f >= NFILT) return;
    float s = 0.f;
    for (int p = 0; p < NFREQ; p++) {
        int m = f*PP + p;
        int mt = m >> 7, r = m & 127;
        #pragma unroll
        for (int sl = 0; sl < 4; sl++)
            s += g_Part[(mt*4 + sl)*128 + r];
    }
    out[f] = s * (1.0f / (float)(NFREQ*NTIME));
}

// ---------------- launch ----------------
extern "C" void kernel_launch(void* const* d_in, const int* in_sizes, int n_in,
                              void* d_out, int out_size) {
    (void)in_sizes; (void)n_in; (void)out_size;
    const float* x   = (const float*)d_in[0];
    const float* Hre = (const float*)d_in[1];
    const float* Him = (const float*)d_in[2];
    float* out = (float*)d_out;

    cudaFuncSetAttribute(k_s1mma, cudaFuncAttributeMaxDynamicSharedMemorySize, SM_TOT);

    k_B1    <<<(PP*KP + 255)/256, 256>>>();
    k_E2    <<<(KFOLD*NQPAD + 255)/256, 256>>>();
    k_P     <<<dim3(5, NFREQ), 256>>>(x);
    k_X     <<<dim3(5, KF),    256>>>();
    k_s1mma <<<dim3(S1LT, NFILT), 512, SM_TOT>>>(Hre, Him);
    k_s2mma <<<dim3(2, S2MT), 512>>>();
    k_fin   <<<1, 128>>>(out);
}